// round 12
// baseline (speedup 1.0000x reference)
#include <cuda_runtime.h>
#include <math.h>

// Problem constants (fixed by the reference)
#define NVAR 4000000
#define KFAC 2000000
#define DV 3
#define DC 6
#define EDGES (NVAR * DV)   // 12,000,000

// Scratch (static; allocation-free rule).
// g_t:   t = tanh(Hsx) per edge, variable-side order (48MB). L2-resident
//        target of K2's random gathers.
// g_acc: per-variable belief accumulator (16MB). Zeroed by K1 (so its
//        sectors are L2-dirty-resident), accumulated by K2 via RED.ADD
//        (L2-side RMW, no write-allocate DRAM traffic), read by K3.
__device__ float g_t[EDGES];
__device__ float g_acc[NVAR];

// ---------------------------------------------------------------------------
// Kernel 1: variable -> factor update fused with tanh + accumulator zeroing.
// One thread per variable. Single-log prior: 0.5*log((mx*px)/(my*py)).
// ---------------------------------------------------------------------------
__global__ void __launch_bounds__(256)
var_update_kernel(const float2* __restrict__ ps,
                  const float2* __restrict__ Min,
                  const float*  __restrict__ Hxs_prev,
                  int n_vars)
{
    int n = blockIdx.x * blockDim.x + threadIdx.x;
    if (n >= n_vars) return;

    float2 m = Min[n];
    float2 p = ps[n];
    float prior = 0.5f * __logf(__fdividef(m.x * p.x, m.y * p.y));

    float h0 = Hxs_prev[3 * n + 0];
    float h1 = Hxs_prev[3 * n + 1];
    float h2 = Hxs_prev[3 * n + 2];

    bool i0 = isinf(h0), i1 = isinf(h1), i2 = isinf(h2);
    int sure = (int)i0 + (int)i1 + (int)i2;

    float o0, o1, o2;
    if (sure == 0) {
        float ll = (h0 + h1) + h2;
        o0 = prior + ll - h0;
        o1 = prior + ll - h1;
        o2 = prior + ll - h2;
    } else {
        float ll = (i0 ? 0.0f : h0) + (i1 ? 0.0f : h1) + (i2 ? 0.0f : h2);
        float ss = (i0 ? h0 : 0.0f) + (i1 ? h1 : 0.0f) + (i2 ? h2 : 0.0f);
        if (sure == 1) {
            float pl = prior + ll;
            o0 = i0 ? pl : ss;
            o1 = i1 ? pl : ss;
            o2 = i2 ? pl : ss;
        } else {
            float v = isnan(ss) ? 0.0f : (prior + ss);
            o0 = v; o1 = v; o2 = v;
        }
    }
    // store tanh(Hsx): tanh(+-inf)=+-1, tanh(nan)=nan -> semantics preserved
    g_t[3 * n + 0] = tanhf(o0);
    g_t[3 * n + 1] = tanhf(o1);
    g_t[3 * n + 2] = tanhf(o2);

    // zero the belief accumulator (keeps its sectors dirty-resident in L2)
    g_acc[n] = 0.0f;
}

// ---------------------------------------------------------------------------
// Kernel 2: factor update, message delivery via atomics. One factor/thread.
// 6 random gathers of t, full per-edge messages computed in registers, then
// 6 RED.ADD.F32 into the per-variable accumulator (variable = edge_slot/3).
// atanh(pn/t) = 0.5*log((t+pn)/(t-pn)): sign-safe, |pn|==|t| -> +-inf.
// ---------------------------------------------------------------------------
__global__ void __launch_bounds__(256)
fac_update_kernel(const int* __restrict__ inv_perm,
                  const int* __restrict__ x,
                  int n_fac)
{
    int a = blockIdx.x * blockDim.x + threadIdx.x;
    if (a >= n_fac) return;

    const int2* ip2 = (const int2*)(inv_perm + 6 * a);   // 24B stride: 8B aligned
    int2 b0 = __ldcs(ip2 + 0);
    int2 b1 = __ldcs(ip2 + 1);
    int2 b2 = __ldcs(ip2 + 2);
    int idx[6] = {b0.x, b0.y, b1.x, b1.y, b2.x, b2.y};

    // 6 gathers issued back-to-back
    float v[6];
#pragma unroll
    for (int k = 0; k < 6; k++)
        v[k] = __ldcg(&g_t[idx[k]]);

    float pn = 1.0f - 2.0f * (float)__ldcs(&x[a]);
    int nz = 0;
#pragma unroll
    for (int k = 0; k < 6; k++) {
        bool z = (v[k] == 0.0f);
        nz += (int)z;
        pn *= z ? 1.0f : v[k];
    }

    float msg[6];
    if (nz == 0) {
#pragma unroll
        for (int k = 0; k < 6; k++)
            msg[k] = 0.5f * __logf(__fdividef(v[k] + pn, v[k] - pn));
    } else if (nz == 1) {
        float ath = 0.5f * __logf(__fdividef(1.0f + pn, 1.0f - pn));
#pragma unroll
        for (int k = 0; k < 6; k++)
            msg[k] = (v[k] == 0.0f) ? ath : 0.0f;
    } else {
#pragma unroll
        for (int k = 0; k < 6; k++)
            msg[k] = 0.0f;
    }

    // deliver: RED.ADD to L2-resident accumulator, variable id = slot/3
#pragma unroll
    for (int k = 0; k < 6; k++)
        atomicAdd(&g_acc[idx[k] / 3], msg[k]);
}

// ---------------------------------------------------------------------------
// Kernel 3: output beliefs. Pure streaming: read acc (16MB), write M (32MB).
// s=+inf -> d=1 (matches reference: d only nan on mixed +-inf messages,
// which requires five exactly-saturated tanh's in one factor -- absent).
// ---------------------------------------------------------------------------
__global__ void __launch_bounds__(256)
output_kernel(float2* __restrict__ Mout, int n_vars)
{
    int n = blockIdx.x * blockDim.x + threadIdx.x;
    if (n >= n_vars) return;

    float d = tanhf(g_acc[n]);

    float2 o;
    o.x = 0.5f + 0.5f * d;
    o.y = 0.5f - 0.5f * d;
    Mout[n] = o;
}

// ---------------------------------------------------------------------------
// Launch. Inputs: ps[N,2] f32, Min[N,2] f32, Hxs_prev[N,3] f32, x[K,1] i32,
// perm[E] i32 (unused), inv_perm[E] i32. Output: M_out[N,2] f32.
// ---------------------------------------------------------------------------
extern "C" void kernel_launch(void* const* d_in, const int* in_sizes, int n_in,
                              void* d_out, int out_size)
{
    const float2* ps       = (const float2*)d_in[0];
    const float2* Min      = (const float2*)d_in[1];
    const float*  Hxs_prev = (const float*)d_in[2];
    const int*    x        = (const int*)d_in[3];
    const int*    inv_perm = (const int*)d_in[5];

    int n_vars = in_sizes[0] / 2;   // 4,000,000
    int n_fac  = in_sizes[3];       // 2,000,000

    const int T = 256;
    var_update_kernel<<<(n_vars + T - 1) / T, T>>>(ps, Min, Hxs_prev, n_vars);
    fac_update_kernel<<<(n_fac + T - 1) / T, T>>>(inv_perm, x, n_fac);
    output_kernel<<<(n_vars + T - 1) / T, T>>>((float2*)d_out, n_vars);
}

// round 13
// speedup vs baseline: 1.0298x; 1.0298x over previous
#include <cuda_runtime.h>
#include <math.h>

// Problem constants (fixed by the reference)
#define NVAR 4000000
#define KFAC 2000000
#define DV 3
#define DC 6
#define EDGES (NVAR * DV)   // 12,000,000

// Scratch (static; allocation-free rule).
// g_t:   t = tanh(Hsx) per edge, variable-side order (48MB). L2-resident
//        target of K2's random gathers.
// g_agg: per-factor packed aggregate (8MB): pn float bits with the low 2
//        mantissa bits replaced by min(nz,3) (rel perturbation ~2.4e-7).
__device__ float        g_t[EDGES];
__device__ unsigned int g_agg[KFAC];

// ---------------------------------------------------------------------------
// Kernel 1: variable -> factor update fused with tanh. One thread/variable.
// Single-log prior: 0.5*log((mx*px)/(my*py)), args in [0.0025, 1].
// Stores bypass L1 (__stcg): consumers read via L2; keeps K1's L1 for reads.
// ---------------------------------------------------------------------------
__global__ void __launch_bounds__(256)
var_update_kernel(const float2* __restrict__ ps,
                  const float2* __restrict__ Min,
                  const float*  __restrict__ Hxs_prev,
                  int n_vars)
{
    int n = blockIdx.x * blockDim.x + threadIdx.x;
    if (n >= n_vars) return;

    float2 m = Min[n];
    float2 p = ps[n];
    float prior = 0.5f * __logf(__fdividef(m.x * p.x, m.y * p.y));

    float h0 = Hxs_prev[3 * n + 0];
    float h1 = Hxs_prev[3 * n + 1];
    float h2 = Hxs_prev[3 * n + 2];

    bool i0 = isinf(h0), i1 = isinf(h1), i2 = isinf(h2);
    int sure = (int)i0 + (int)i1 + (int)i2;

    float o0, o1, o2;
    if (sure == 0) {
        float ll = (h0 + h1) + h2;
        o0 = prior + ll - h0;
        o1 = prior + ll - h1;
        o2 = prior + ll - h2;
    } else {
        float ll = (i0 ? 0.0f : h0) + (i1 ? 0.0f : h1) + (i2 ? 0.0f : h2);
        float ss = (i0 ? h0 : 0.0f) + (i1 ? h1 : 0.0f) + (i2 ? h2 : 0.0f);
        if (sure == 1) {
            float pl = prior + ll;
            o0 = i0 ? pl : ss;
            o1 = i1 ? pl : ss;
            o2 = i2 ? pl : ss;
        } else {
            float v = isnan(ss) ? 0.0f : (prior + ss);
            o0 = v; o1 = v; o2 = v;
        }
    }
    // store tanh(Hsx): tanh(+-inf)=+-1, tanh(nan)=nan -> semantics preserved
    __stcg(&g_t[3 * n + 0], tanhf(o0));
    __stcg(&g_t[3 * n + 1], tanhf(o1));
    __stcg(&g_t[3 * n + 2], tanhf(o2));
}

// ---------------------------------------------------------------------------
// Kernel 2: factor aggregates. ONE factor per thread (measured best: lightest
// threads -> most warps feeding the L1tex queue). 6 indices via 3x int2
// (8B-aligned at 24B factor stride), 6 gathers back-to-back, contiguous
// 4B packed aggregate store.
// ---------------------------------------------------------------------------
__device__ __forceinline__ unsigned int pack_agg(float pn, int nz)
{
    return (__float_as_uint(pn) & ~3u) | (unsigned int)(nz < 3 ? nz : 3);
}

__global__ void __launch_bounds__(256)
fac_aggregate_kernel(const int* __restrict__ inv_perm,
                     const int* __restrict__ x,
                     int n_fac)
{
    int a = blockIdx.x * blockDim.x + threadIdx.x;
    if (a >= n_fac) return;

    const int2* ip2 = (const int2*)(inv_perm + 6 * a);   // 24B stride: 8B aligned
    int2 b0 = __ldcs(ip2 + 0);
    int2 b1 = __ldcs(ip2 + 1);
    int2 b2 = __ldcs(ip2 + 2);

    // 6 gathers issued back-to-back
    float v0 = __ldcg(&g_t[b0.x]);
    float v1 = __ldcg(&g_t[b0.y]);
    float v2 = __ldcg(&g_t[b1.x]);
    float v3 = __ldcg(&g_t[b1.y]);
    float v4 = __ldcg(&g_t[b2.x]);
    float v5 = __ldcg(&g_t[b2.y]);

    float pn = 1.0f - 2.0f * (float)__ldcs(&x[a]);
    int nz = 0;

    bool z;
    z = (v0 == 0.0f); nz += (int)z; pn *= z ? 1.0f : v0;
    z = (v1 == 0.0f); nz += (int)z; pn *= z ? 1.0f : v1;
    z = (v2 == 0.0f); nz += (int)z; pn *= z ? 1.0f : v2;
    z = (v3 == 0.0f); nz += (int)z; pn *= z ? 1.0f : v3;
    z = (v4 == 0.0f); nz += (int)z; pn *= z ? 1.0f : v4;
    z = (v5 == 0.0f); nz += (int)z; pn *= z ? 1.0f : v5;

    g_agg[a] = pack_agg(pn, nz);
}

// ---------------------------------------------------------------------------
// per-edge message from self-tanh + packed factor aggregate.
// atanh(pn/t) = 0.5*log((t+pn)/(t-pn)):
//   sign-safe; |pn|==|t| -> +-inf; |pn|>|t| -> nan; nan pn propagates.
// ---------------------------------------------------------------------------
__device__ __forceinline__ float edge_msg(float ts, unsigned int w)
{
    int nz = (int)(w & 3u);
    float pn = __uint_as_float(w & ~3u);
    float r = 0.0f;
    if (nz == 0) {
        r = 0.5f * __logf(__fdividef(ts + pn, ts - pn));
    } else if (nz == 1) {
        if (ts == 0.0f)
            r = 0.5f * __logf(__fdividef(1.0f + pn, 1.0f - pn));
    }
    return r;
}

__device__ __forceinline__ float belief(float h0, float h1, float h2)
{
    float s = (h0 + h1) + h2;
    float d = tanhf(s);
    if (isnan(d)) {
        bool c0 = isinf(h0), c1 = isinf(h1), c2 = isinf(h2);
        if (c0 | c1 | c2) {
            float s2 = (c0 ? 0.0f : h0) + (c1 ? 0.0f : h1) + (c2 ? 0.0f : h2);
            d = tanhf(s2);
        }
    }
    return d;
}

// ---------------------------------------------------------------------------
// Kernel 3: output beliefs. One thread per variable (measured best).
// 3 back-to-back gathers from the 8MB aggregate array; streams via __ldcs.
// ---------------------------------------------------------------------------
__global__ void __launch_bounds__(256)
output_kernel(const int* __restrict__ perm,
              float2* __restrict__ Mout,
              int n_vars)
{
    int n = blockIdx.x * blockDim.x + threadIdx.x;
    if (n >= n_vars) return;

    int e0 = __ldcs(&perm[3 * n + 0]);
    int e1 = __ldcs(&perm[3 * n + 1]);
    int e2 = __ldcs(&perm[3 * n + 2]);

    // factor ids (perm value = factor-side slot 6a+k); gathers back-to-back
    unsigned int w0 = __ldg(&g_agg[e0 / 6]);
    unsigned int w1 = __ldg(&g_agg[e1 / 6]);
    unsigned int w2 = __ldg(&g_agg[e2 / 6]);

    float t0 = __ldcs(&g_t[3 * n + 0]);
    float t1 = __ldcs(&g_t[3 * n + 1]);
    float t2 = __ldcs(&g_t[3 * n + 2]);

    float m0 = edge_msg(t0, w0);
    float m1 = edge_msg(t1, w1);
    float m2 = edge_msg(t2, w2);

    float d = belief(m0, m1, m2);

    float2 o;
    o.x = 0.5f + 0.5f * d;
    o.y = 0.5f - 0.5f * d;
    Mout[n] = o;
}

// ---------------------------------------------------------------------------
// Launch. Inputs: ps[N,2] f32, Min[N,2] f32, Hxs_prev[N,3] f32, x[K,1] i32,
// perm[E] i32, inv_perm[E] i32. Output: M_out[N,2] f32.
// ---------------------------------------------------------------------------
extern "C" void kernel_launch(void* const* d_in, const int* in_sizes, int n_in,
                              void* d_out, int out_size)
{
    const float2* ps       = (const float2*)d_in[0];
    const float2* Min      = (const float2*)d_in[1];
    const float*  Hxs_prev = (const float*)d_in[2];
    const int*    x        = (const int*)d_in[3];
    const int*    perm     = (const int*)d_in[4];
    const int*    inv_perm = (const int*)d_in[5];

    int n_vars = in_sizes[0] / 2;   // 4,000,000
    int n_fac  = in_sizes[3];       // 2,000,000

    const int T = 256;
    var_update_kernel<<<(n_vars + T - 1) / T, T>>>(ps, Min, Hxs_prev, n_vars);
    fac_aggregate_kernel<<<(n_fac + T - 1) / T, T>>>(inv_perm, x, n_fac);
    output_kernel<<<(n_vars + T - 1) / T, T>>>(perm, (float2*)d_out, n_vars);
}

// round 14
// speedup vs baseline: 1.0315x; 1.0017x over previous
#include <cuda_runtime.h>
#include <math.h>

// Problem constants (fixed by the reference)
#define NVAR 4000000
#define KFAC 2000000
#define DV 3
#define DC 6
#define EDGES (NVAR * DV)   // 12,000,000

// Scratch (static; allocation-free rule).
// g_t:   t = tanh(Hsx) per edge, variable-side order (48MB). L2-resident
//        target of K2's random gathers.
// g_agg: per-factor packed aggregate (8MB): pn float bits with the low 2
//        mantissa bits replaced by min(nz,3) (rel perturbation ~2.4e-7).
__device__ float        g_t[EDGES];
__device__ unsigned int g_agg[KFAC];

// ---------------------------------------------------------------------------
// Kernel 1: variable -> factor update fused with tanh. One thread/variable.
// Single-log prior: 0.5*log((mx*px)/(my*py)), args in [0.0025, 1].
// Plain loads/stores measured best.
// ---------------------------------------------------------------------------
__global__ void __launch_bounds__(256)
var_update_kernel(const float2* __restrict__ ps,
                  const float2* __restrict__ Min,
                  const float*  __restrict__ Hxs_prev,
                  int n_vars)
{
    int n = blockIdx.x * blockDim.x + threadIdx.x;
    if (n >= n_vars) return;

    float2 m = Min[n];
    float2 p = ps[n];
    float prior = 0.5f * __logf(__fdividef(m.x * p.x, m.y * p.y));

    float h0 = Hxs_prev[3 * n + 0];
    float h1 = Hxs_prev[3 * n + 1];
    float h2 = Hxs_prev[3 * n + 2];

    bool i0 = isinf(h0), i1 = isinf(h1), i2 = isinf(h2);
    int sure = (int)i0 + (int)i1 + (int)i2;

    float o0, o1, o2;
    if (sure == 0) {
        float ll = (h0 + h1) + h2;
        o0 = prior + ll - h0;
        o1 = prior + ll - h1;
        o2 = prior + ll - h2;
    } else {
        float ll = (i0 ? 0.0f : h0) + (i1 ? 0.0f : h1) + (i2 ? 0.0f : h2);
        float ss = (i0 ? h0 : 0.0f) + (i1 ? h1 : 0.0f) + (i2 ? h2 : 0.0f);
        if (sure == 1) {
            float pl = prior + ll;
            o0 = i0 ? pl : ss;
            o1 = i1 ? pl : ss;
            o2 = i2 ? pl : ss;
        } else {
            float v = isnan(ss) ? 0.0f : (prior + ss);
            o0 = v; o1 = v; o2 = v;
        }
    }
    // store tanh(Hsx): tanh(+-inf)=+-1, tanh(nan)=nan -> semantics preserved
    g_t[3 * n + 0] = tanhf(o0);
    g_t[3 * n + 1] = tanhf(o1);
    g_t[3 * n + 2] = tanhf(o2);
}

// ---------------------------------------------------------------------------
// Kernel 2: factor aggregates. ONE factor per thread (measured best: lightest
// threads -> most warps feeding the L1tex queue). 6 indices via 3x int2
// (8B-aligned at 24B factor stride), 6 gathers back-to-back, contiguous
// 4B packed aggregate store.
// ---------------------------------------------------------------------------
__device__ __forceinline__ unsigned int pack_agg(float pn, int nz)
{
    return (__float_as_uint(pn) & ~3u) | (unsigned int)(nz < 3 ? nz : 3);
}

__global__ void __launch_bounds__(256)
fac_aggregate_kernel(const int* __restrict__ inv_perm,
                     const int* __restrict__ x,
                     int n_fac)
{
    int a = blockIdx.x * blockDim.x + threadIdx.x;
    if (a >= n_fac) return;

    const int2* ip2 = (const int2*)(inv_perm + 6 * a);   // 24B stride: 8B aligned
    int2 b0 = __ldcs(ip2 + 0);
    int2 b1 = __ldcs(ip2 + 1);
    int2 b2 = __ldcs(ip2 + 2);

    // 6 gathers issued back-to-back
    float v0 = __ldcg(&g_t[b0.x]);
    float v1 = __ldcg(&g_t[b0.y]);
    float v2 = __ldcg(&g_t[b1.x]);
    float v3 = __ldcg(&g_t[b1.y]);
    float v4 = __ldcg(&g_t[b2.x]);
    float v5 = __ldcg(&g_t[b2.y]);

    float pn = 1.0f - 2.0f * (float)__ldcs(&x[a]);
    int nz = 0;

    bool z;
    z = (v0 == 0.0f); nz += (int)z; pn *= z ? 1.0f : v0;
    z = (v1 == 0.0f); nz += (int)z; pn *= z ? 1.0f : v1;
    z = (v2 == 0.0f); nz += (int)z; pn *= z ? 1.0f : v2;
    z = (v3 == 0.0f); nz += (int)z; pn *= z ? 1.0f : v3;
    z = (v4 == 0.0f); nz += (int)z; pn *= z ? 1.0f : v4;
    z = (v5 == 0.0f); nz += (int)z; pn *= z ? 1.0f : v5;

    g_agg[a] = pack_agg(pn, nz);
}

// ---------------------------------------------------------------------------
// per-edge message from self-tanh + packed factor aggregate.
// atanh(pn/t) = 0.5*log((t+pn)/(t-pn)):
//   sign-safe; |pn|==|t| -> +-inf; |pn|>|t| -> nan; nan pn propagates.
// ---------------------------------------------------------------------------
__device__ __forceinline__ float edge_msg(float ts, unsigned int w)
{
    int nz = (int)(w & 3u);
    float pn = __uint_as_float(w & ~3u);
    float r = 0.0f;
    if (nz == 0) {
        r = 0.5f * __logf(__fdividef(ts + pn, ts - pn));
    } else if (nz == 1) {
        if (ts == 0.0f)
            r = 0.5f * __logf(__fdividef(1.0f + pn, 1.0f - pn));
    }
    return r;
}

__device__ __forceinline__ float belief(float h0, float h1, float h2)
{
    float s = (h0 + h1) + h2;
    float d = tanhf(s);
    if (isnan(d)) {
        bool c0 = isinf(h0), c1 = isinf(h1), c2 = isinf(h2);
        if (c0 | c1 | c2) {
            float s2 = (c0 ? 0.0f : h0) + (c1 ? 0.0f : h1) + (c2 ? 0.0f : h2);
            d = tanhf(s2);
        }
    }
    return d;
}

// ---------------------------------------------------------------------------
// Kernel 3: output beliefs. One thread per variable (measured best).
// 3 back-to-back gathers from the 8MB aggregate array; streams via __ldcs.
// ---------------------------------------------------------------------------
__global__ void __launch_bounds__(256)
output_kernel(const int* __restrict__ perm,
              float2* __restrict__ Mout,
              int n_vars)
{
    int n = blockIdx.x * blockDim.x + threadIdx.x;
    if (n >= n_vars) return;

    int e0 = __ldcs(&perm[3 * n + 0]);
    int e1 = __ldcs(&perm[3 * n + 1]);
    int e2 = __ldcs(&perm[3 * n + 2]);

    // factor ids (perm value = factor-side slot 6a+k); gathers back-to-back
    unsigned int w0 = __ldg(&g_agg[e0 / 6]);
    unsigned int w1 = __ldg(&g_agg[e1 / 6]);
    unsigned int w2 = __ldg(&g_agg[e2 / 6]);

    float t0 = __ldcs(&g_t[3 * n + 0]);
    float t1 = __ldcs(&g_t[3 * n + 1]);
    float t2 = __ldcs(&g_t[3 * n + 2]);

    float m0 = edge_msg(t0, w0);
    float m1 = edge_msg(t1, w1);
    float m2 = edge_msg(t2, w2);

    float d = belief(m0, m1, m2);

    float2 o;
    o.x = 0.5f + 0.5f * d;
    o.y = 0.5f - 0.5f * d;
    Mout[n] = o;
}

// ---------------------------------------------------------------------------
// Launch. Inputs: ps[N,2] f32, Min[N,2] f32, Hxs_prev[N,3] f32, x[K,1] i32,
// perm[E] i32, inv_perm[E] i32. Output: M_out[N,2] f32.
// ---------------------------------------------------------------------------
extern "C" void kernel_launch(void* const* d_in, const int* in_sizes, int n_in,
                              void* d_out, int out_size)
{
    const float2* ps       = (const float2*)d_in[0];
    const float2* Min      = (const float2*)d_in[1];
    const float*  Hxs_prev = (const float*)d_in[2];
    const int*    x        = (const int*)d_in[3];
    const int*    perm     = (const int*)d_in[4];
    const int*    inv_perm = (const int*)d_in[5];

    int n_vars = in_sizes[0] / 2;   // 4,000,000
    int n_fac  = in_sizes[3];       // 2,000,000

    const int T = 256;
    var_update_kernel<<<(n_vars + T - 1) / T, T>>>(ps, Min, Hxs_prev, n_vars);
    fac_aggregate_kernel<<<(n_fac + T - 1) / T, T>>>(inv_perm, x, n_fac);
    output_kernel<<<(n_vars + T - 1) / T, T>>>(perm, (float2*)d_out, n_vars);
}